// round 9
// baseline (speedup 1.0000x reference)
#include <cuda_runtime.h>
#include <cuda_bf16.h>
#include <cstdint>
#include <math.h>

#define NF 512
#define NFIELD 30
#define KDIM 40
#define MT 64           // rows per CTA
#define NT 256          // n per sweep (2 sweeps)
#define KC 128          // k per chunk
#define NTHREADS 512
#define NCHUNK 8        // 2 sweeps x 4 k-chunks

// ---- smem layout (bytes) ----
#define SM_X      0
#define SM_X_BYTES (MT * NF * 2)            // 65536
#define SM_B      (SM_X + SM_X_BYTES)
#define SM_B_SLOT (NT * KC * 2)             // 65536
#define SM_ACC    (SM_B + 2 * SM_B_SLOT)    // 196608
#define SM_TOT    (SM_ACC + MT * 4)         // 196864

// Precomputed interaction matrix G = 0.5*C, zero diag, bf16, symmetric.
__device__ __nv_bfloat16 g_G[NF * NF];

// ---------------- helpers ----------------
__device__ __forceinline__ uint32_t smem_u32(const void* p) {
    uint32_t a;
    asm("{ .reg .u64 t; cvta.to.shared.u64 t, %1; cvt.u32.u64 %0, t; }" : "=r"(a) : "l"(p));
    return a;
}
__device__ __forceinline__ uint32_t sw128(uint32_t b) { return b ^ ((b >> 3) & 0x70); }
// X tile: blocked atoms (8 rows x 64 bf16 = 1024B); 8 atoms per 64-col group
__device__ __forceinline__ uint32_t aByte(int r, int k) {
    return (uint32_t)((((r >> 3) + (k >> 6) * 8) << 10) + ((r & 7) << 7) + ((k & 63) << 1));
}
__device__ __forceinline__ void ldsm4(uint32_t* r, uint32_t addr) {
    asm volatile("ldmatrix.sync.aligned.m8n8.x4.shared.b16 {%0,%1,%2,%3}, [%4];"
                 : "=r"(r[0]), "=r"(r[1]), "=r"(r[2]), "=r"(r[3]) : "r"(addr));
}
__device__ __forceinline__ void mma16816(float* c, const uint32_t* a, const uint32_t* b) {
    asm volatile(
        "mma.sync.aligned.m16n8k16.row.col.f32.bf16.bf16.f32 "
        "{%0,%1,%2,%3}, {%4,%5,%6,%7}, {%8,%9}, {%0,%1,%2,%3};"
        : "+f"(c[0]), "+f"(c[1]), "+f"(c[2]), "+f"(c[3])
        : "r"(a[0]), "r"(a[1]), "r"(a[2]), "r"(a[3]), "r"(b[0]), "r"(b[1]));
}
__device__ __forceinline__ void cp16(uint32_t dst, const void* src) {
    asm volatile("cp.async.cg.shared.global [%0], [%1], 16;" :: "r"(dst), "l"(src) : "memory");
}
#define CP_COMMIT() asm volatile("cp.async.commit_group;" ::: "memory")

// ---------------------------------------------------------------------------
// Kernel 1: G symmetric — compute i>=j, write both mirrors.
// ---------------------------------------------------------------------------
__global__ void build_G_kernel(const float* __restrict__ v, const int* __restrict__ f2f) {
    int j = blockIdx.x;
    int i = threadIdx.x;
    if (i < j) return;
    int fj = __ldg(&f2f[j]);
    int fi = __ldg(&f2f[i]);
    const float4* a  = reinterpret_cast<const float4*>(v + ((size_t)i * NFIELD + fj) * KDIM);
    const float4* bp = reinterpret_cast<const float4*>(v + ((size_t)j * NFIELD + fi) * KDIM);
    float s = 0.f;
#pragma unroll
    for (int t = 0; t < KDIM / 4; t++) {
        float4 av = a[t], bv = bp[t];
        s = fmaf(av.x, bv.x, s);
        s = fmaf(av.y, bv.y, s);
        s = fmaf(av.z, bv.z, s);
        s = fmaf(av.w, bv.w, s);
    }
    s *= 0.5f;
    if (i == j) s = 0.f;
    __nv_bfloat16 h = __float2bfloat16(s);
    g_G[(size_t)j * NF + i] = h;
    g_G[(size_t)i * NF + j] = h;
}

// ---------------------------------------------------------------------------
// Kernel 2: HMMA quadratic form. 16 warps, warp tile m16 x n64, MT=64.
//   8 chunks of k=128 (2 n-sweeps x 4); 2-slot cp.async double buffer;
//   one barrier per chunk. acc = 32 regs -> scheduling headroom.
// ---------------------------------------------------------------------------
__global__ __launch_bounds__(NTHREADS, 1)
void ffm_hmma_kernel(const float* __restrict__ X, const float* __restrict__ w1g,
                     const float* __restrict__ bg, float* __restrict__ out) {
    extern __shared__ __align__(1024) char smem[];
    const int tid  = threadIdx.x;
    const int lane = tid & 31;
    const int wid  = tid >> 5;
    const int wm   = wid & 3;    // 4 x 16 rows
    const int wn   = wid >> 2;   // 4 x 64 cols

    uint32_t sb = smem_u32(smem);
    float* accs = reinterpret_cast<float*>(smem + SM_ACC);
    if (tid < MT) accs[tid] = 0.f;

    // ---- G chunk stager: chunk t -> jt = t>>2 (n-half), kc = t&3 ----
    // B slot layout: 256 n-rows x 128 k bf16; atom = (n>>3) + (k>>6)*32.
    auto issue = [&](int t) {
        int jt = t >> 2, kc = t & 3;
        uint32_t slot = sb + SM_B + (t & 1) * SM_B_SLOT;
        const __nv_bfloat16* gb = g_G + (size_t)jt * NT * NF + kc * KC;
#pragma unroll
        for (int i = 0; i < 8; i++) {
            int flat = tid + i * NTHREADS;       // 0..4095
            int n = flat >> 4, kq = flat & 15;   // kq: 16B unit (8 bf16)
            uint32_t byte = ((uint32_t)((n >> 3) + (kq >> 3) * 32) << 10)
                          + ((n & 7) << 7) + ((kq & 7) << 4);
            cp16(slot + sw128(byte), gb + (size_t)n * NF + kq * 8);
        }
        CP_COMMIT();
    };
    issue(0);

    // ---- X prologue: 64 x 512 f32 -> bf16, swizzled blocked atoms ----
    const float4* Xg = reinterpret_cast<const float4*>(X + (size_t)blockIdx.x * MT * NF);
#pragma unroll 4
    for (int it = 0; it < 16; it++) {
        int f = tid + it * NTHREADS;
        int r = f >> 7;             // 128 float4 per row
        int k = (f & 127) * 4;
        float4 x4 = Xg[f];
        __nv_bfloat162 lo, hi;
        lo.x = __float2bfloat16(x4.x); lo.y = __float2bfloat16(x4.y);
        hi.x = __float2bfloat16(x4.z); hi.y = __float2bfloat16(x4.w);
        uint2 u;
        u.x = *reinterpret_cast<uint32_t*>(&lo);
        u.y = *reinterpret_cast<uint32_t*>(&hi);
        *reinterpret_cast<uint2*>(smem + SM_X + sw128(aByte(r, k))) = u;
    }

    // ---- per-lane ldsm address constants (swizzle folded: disjoint bits) ----
    // k within chunk: ks*16 (+ lane-dependent); ks = 0..7 spans 2 k-groups.
    uint32_t koffA[8], koffB[8];
#pragma unroll
    for (int ks = 0; ks < 8; ks++) {
        uint32_t kin = ((uint32_t)((lane >> 4) << 4) | ((ks & 3) << 5)) ^ ((lane & 7) << 4);
        koffA[ks] = kin + ((uint32_t)(ks >> 2) << 13);   // A k-group stride: 8 atoms
        uint32_t kbn = ((uint32_t)(((lane >> 3) & 1) << 4) | ((ks & 3) << 5)) ^ ((lane & 7) << 4);
        koffB[ks] = kbn + ((uint32_t)(ks >> 2) << 15);   // B k-group stride: 32 atoms
    }
    const uint32_t aRowB = sb + SM_X +
        (uint32_t)(((wm * 2 + ((lane >> 3) & 1)) << 10) | ((lane & 7) << 7));
    uint32_t bRowB[4];
#pragma unroll
    for (int nf = 0; nf < 4; nf++)
        bRowB[nf] = (uint32_t)(((wn * 8 + nf * 2 + ((lane >> 4) & 1)) << 10) | ((lane & 7) << 7));

    float acc[8][4];
    const float bias0 = bg[0];

#pragma unroll 1
    for (int t = 0; t < NCHUNK; t++) {
        asm volatile("cp.async.wait_group 0;" ::: "memory");
        __syncthreads();   // chunk t visible; all warps done reading chunk t-1
        if (t < NCHUNK - 1) issue(t + 1);   // fetch t+1 overlaps compute t

        if ((t & 3) == 0) {
            // init accumulators with w1 (folds linear term in)
            int jt = t >> 2;
#pragma unroll
            for (int nf8 = 0; nf8 < 8; nf8++) {
                int c = jt * NT + wn * 64 + nf8 * 8 + (lane & 3) * 2;
                acc[nf8][0] = __ldg(&w1g[c]);
                acc[nf8][1] = __ldg(&w1g[c + 1]);
                acc[nf8][2] = acc[nf8][0];
                acc[nf8][3] = acc[nf8][1];
            }
        }

        uint32_t slot = sb + SM_B + (uint32_t)(t & 1) * SM_B_SLOT;
        uint32_t aB = aRowB + ((uint32_t)(t & 3) << 14);   // 2 k-groups per chunk
        uint32_t bB[4];
#pragma unroll
        for (int nf = 0; nf < 4; nf++) bB[nf] = slot + bRowB[nf];

#pragma unroll
        for (int ks = 0; ks < 8; ks++) {
            uint32_t a[4], b[4][4];
            ldsm4(a, aB + koffA[ks]);
#pragma unroll
            for (int nf = 0; nf < 4; nf++) ldsm4(b[nf], bB[nf] + koffB[ks]);
#pragma unroll
            for (int nf = 0; nf < 4; nf++) {
                mma16816(acc[2 * nf],     a, &b[nf][0]);
                mma16816(acc[2 * nf + 1], a, &b[nf][2]);
            }
        }

        if ((t & 3) == 3) {
            // ---- epilogue for this n-sweep: sum += acc . x  (w1 already in) ----
            int jt = t >> 2;
            int r0 = wm * 16 + (lane >> 2);
            int r1 = r0 + 8;
            float pA = 0.f, pB = 0.f;
#pragma unroll
            for (int nf8 = 0; nf8 < 8; nf8++) {
                int c = jt * NT + wn * 64 + nf8 * 8 + (lane & 3) * 2;
                uint32_t xa = *reinterpret_cast<uint32_t*>(smem + SM_X + sw128(aByte(r0, c)));
                uint32_t xb = *reinterpret_cast<uint32_t*>(smem + SM_X + sw128(aByte(r1, c)));
                float x0 = __uint_as_float(xa << 16);
                float x1 = __uint_as_float(xa & 0xffff0000u);
                float y0 = __uint_as_float(xb << 16);
                float y1 = __uint_as_float(xb & 0xffff0000u);
                pA = fmaf(acc[nf8][0], x0, pA);
                pA = fmaf(acc[nf8][1], x1, pA);
                pB = fmaf(acc[nf8][2], y0, pB);
                pB = fmaf(acc[nf8][3], y1, pB);
            }
            pA += __shfl_xor_sync(0xffffffffu, pA, 1);
            pA += __shfl_xor_sync(0xffffffffu, pA, 2);
            pB += __shfl_xor_sync(0xffffffffu, pB, 1);
            pB += __shfl_xor_sync(0xffffffffu, pB, 2);
            if ((lane & 3) == 0) {
                atomicAdd(&accs[r0], pA);
                atomicAdd(&accs[r1], pB);
            }
        }
    }

    __syncthreads();
    if (tid < MT) {
        float logit = accs[tid] + bias0;
        out[blockIdx.x * MT + tid] = 1.f / (1.f + expf(-logit));
    }
}

// ---------------------------------------------------------------------------
// kernel_launch
//   inputs: X [B,512] f32, w1 [512,1] f32, b [1] f32,
//           v [512,30,40] f32, feature2field [512] i32 ; output [B] f32
// ---------------------------------------------------------------------------
extern "C" void kernel_launch(void* const* d_in, const int* in_sizes, int n_in,
                              void* d_out, int out_size) {
    const float* X   = (const float*)d_in[0];
    const float* w1  = (const float*)d_in[1];
    const float* b   = (const float*)d_in[2];
    const float* v   = (const float*)d_in[3];
    const int*   f2f = (const int*)d_in[4];
    float* out = (float*)d_out;
    (void)n_in; (void)out_size;

    int Brows = in_sizes[0] / NF;

    static bool attr_set = false;
    if (!attr_set) {
        cudaFuncSetAttribute(ffm_hmma_kernel,
                             cudaFuncAttributeMaxDynamicSharedMemorySize, SM_TOT);
        attr_set = true;
    }

    build_G_kernel<<<NF, NF>>>(v, f2f);
    ffm_hmma_kernel<<<Brows / MT, NTHREADS, SM_TOT>>>(X, w1, b, out);
}

// round 10
// speedup vs baseline: 1.2226x; 1.2226x over previous
#include <cuda_runtime.h>
#include <cuda_bf16.h>
#include <cstdint>
#include <math.h>

#define NF 512
#define NFIELD 30
#define KDIM 40
#define MT 128          // rows per CTA
#define NT 256          // n per sweep (2 sweeps)
#define KC 64           // k per chunk
#define NTHREADS 512
#define NCHUNK 16       // 2 sweeps x 8 k-chunks
#define CHUNK_BYTES (NT * KC * 2)           // 32768

// ---- smem layout (bytes) ----
#define SM_X      0
#define SM_X_BYTES (MT * NF * 2)            // 131072
#define SM_B      (SM_X + SM_X_BYTES)
#define SM_B_SLOT CHUNK_BYTES               // 32768
#define SM_ACC    (SM_B + 3 * SM_B_SLOT)    // 229376
#define SM_MBAR   (SM_ACC + MT * 4)         // 229888
#define SM_TOT    (SM_MBAR + 64)

// G in bulk-DMA-ready tiled+swizzled layout: chunk u = (n>>8)*8 + (k>>6),
// within-chunk bytes laid out exactly as the smem B slot expects.
__device__ __align__(128) unsigned char g_Gt[NCHUNK * CHUNK_BYTES];

// ---------------- helpers ----------------
__device__ __forceinline__ uint32_t smem_u32(const void* p) {
    uint32_t a;
    asm("{ .reg .u64 t; cvta.to.shared.u64 t, %1; cvt.u32.u64 %0, t; }" : "=r"(a) : "l"(p));
    return a;
}
__device__ __forceinline__ uint32_t sw128(uint32_t b) { return b ^ ((b >> 3) & 0x70); }
// X tile: blocked atoms (8 rows x 64 bf16 = 1024B); atom = (r>>3) + (k>>6)*16
__device__ __forceinline__ uint32_t aByte(int r, int k) {
    return (uint32_t)((((r >> 3) + (k >> 6) * 16) << 10) + ((r & 7) << 7) + ((k & 63) << 1));
}
__device__ __forceinline__ void ldsm4(uint32_t* r, uint32_t addr) {
    asm volatile("ldmatrix.sync.aligned.m8n8.x4.shared.b16 {%0,%1,%2,%3}, [%4];"
                 : "=r"(r[0]), "=r"(r[1]), "=r"(r[2]), "=r"(r[3]) : "r"(addr));
}
__device__ __forceinline__ void mma16816(float* c, const uint32_t* a, const uint32_t* b) {
    asm volatile(
        "mma.sync.aligned.m16n8k16.row.col.f32.bf16.bf16.f32 "
        "{%0,%1,%2,%3}, {%4,%5,%6,%7}, {%8,%9}, {%0,%1,%2,%3};"
        : "+f"(c[0]), "+f"(c[1]), "+f"(c[2]), "+f"(c[3])
        : "r"(a[0]), "r"(a[1]), "r"(a[2]), "r"(a[3]), "r"(b[0]), "r"(b[1]));
}
#define MBAR_INIT(mb, c) asm volatile("mbarrier.init.shared.b64 [%0], %1;" :: "r"(mb), "r"(c) : "memory")
#define MBAR_EXPECT_TX(mb, bytes) \
    asm volatile("mbarrier.arrive.expect_tx.shared.b64 _, [%0], %1;" :: "r"(mb), "r"(bytes) : "memory")
__device__ __forceinline__ void bulk_g2s(uint32_t dst, const void* src, uint32_t bytes, uint32_t mb) {
    asm volatile(
        "cp.async.bulk.shared::cta.global.mbarrier::complete_tx::bytes [%0], [%1], %2, [%3];"
        :: "r"(dst), "l"(src), "r"(bytes), "r"(mb) : "memory");
}
__device__ __forceinline__ void mbar_wait(uint32_t mb, uint32_t parity) {
    uint32_t done;
    asm volatile(
        "{\n\t.reg .pred p;\n\t"
        "mbarrier.try_wait.parity.acquire.cta.shared::cta.b64 p, [%1], %2;\n\t"
        "selp.b32 %0, 1, 0, p;\n\t}"
        : "=r"(done) : "r"(mb), "r"(parity) : "memory");
    if (!done) {
        asm volatile(
            "{\n\t.reg .pred P1;\n\t"
            "WL_%=:\n\t"
            "mbarrier.try_wait.parity.acquire.cta.shared::cta.b64 P1, [%0], %1, 0x989680;\n\t"
            "@P1 bra.uni WD_%=;\n\t"
            "bra.uni WL_%=;\n\t"
            "WD_%=:\n\t}"
            :: "r"(mb), "r"(parity) : "memory");
    }
}

// ---------------------------------------------------------------------------
// Kernel 1: G symmetric; write BOTH mirrors directly into the tiled+swizzled
// bulk-DMA layout g_Gt. Element (n, k):
//   chunk u = (n>>8)*8 + (k>>6)
//   byte    = sw128( ((n&255)>>3)<<10 | (n&7)<<7 | ((k&63)>>3)<<4 | (k&7)<<1 )
// ---------------------------------------------------------------------------
__device__ __forceinline__ void storeGt(int n, int k, __nv_bfloat16 h) {
    int u = (n >> 8) * 8 + (k >> 6);
    uint32_t byte = ((uint32_t)((n & 255) >> 3) << 10) | ((uint32_t)(n & 7) << 7)
                  | ((uint32_t)((k & 63) >> 3) << 4) | ((uint32_t)(k & 7) << 1);
    *reinterpret_cast<__nv_bfloat16*>(g_Gt + (size_t)u * CHUNK_BYTES + sw128(byte)) = h;
}

__global__ void build_G_kernel(const float* __restrict__ v, const int* __restrict__ f2f) {
    int j = blockIdx.x;
    int i = threadIdx.x;
    if (i < j) return;
    int fj = __ldg(&f2f[j]);
    int fi = __ldg(&f2f[i]);
    const float4* a  = reinterpret_cast<const float4*>(v + ((size_t)i * NFIELD + fj) * KDIM);
    const float4* bp = reinterpret_cast<const float4*>(v + ((size_t)j * NFIELD + fi) * KDIM);
    float s = 0.f;
#pragma unroll
    for (int t = 0; t < KDIM / 4; t++) {
        float4 av = a[t], bv = bp[t];
        s = fmaf(av.x, bv.x, s);
        s = fmaf(av.y, bv.y, s);
        s = fmaf(av.z, bv.z, s);
        s = fmaf(av.w, bv.w, s);
    }
    s *= 0.5f;
    if (i == j) s = 0.f;
    __nv_bfloat16 h = __float2bfloat16(s);
    storeGt(j, i, h);
    storeGt(i, j, h);
}

// ---------------------------------------------------------------------------
// Kernel 2: HMMA quadratic form (R4 structure); B staged by 1 bulk-DMA per
// 32KB chunk (3-slot ring, mbarrier completion) instead of 2048 cp.asyncs.
// ---------------------------------------------------------------------------
__global__ __launch_bounds__(NTHREADS, 1)
void ffm_hmma_kernel(const float* __restrict__ X, const float* __restrict__ w1g,
                     const float* __restrict__ bg, float* __restrict__ out) {
    extern __shared__ __align__(1024) char smem[];
    const int tid  = threadIdx.x;
    const int lane = tid & 31;
    const int wid  = tid >> 5;
    const int wm   = wid & 3;
    const int wn   = wid >> 2;

    uint32_t sb = smem_u32(smem);
    float* accs = reinterpret_cast<float*>(smem + SM_ACC);
    if (tid < MT) accs[tid] = 0.f;

    uint32_t mb[3] = { sb + SM_MBAR, sb + SM_MBAR + 8, sb + SM_MBAR + 16 };
    if (tid == 0) {
        MBAR_INIT(mb[0], 1); MBAR_INIT(mb[1], 1); MBAR_INIT(mb[2], 1);
    }
    __syncthreads();   // mbarrier init visible CTA-wide

    if (tid == 0) {
        MBAR_EXPECT_TX(mb[0], CHUNK_BYTES);
        bulk_g2s(sb + SM_B + 0 * SM_B_SLOT, g_Gt + 0 * (size_t)CHUNK_BYTES, CHUNK_BYTES, mb[0]);
        MBAR_EXPECT_TX(mb[1], CHUNK_BYTES);
        bulk_g2s(sb + SM_B + 1 * SM_B_SLOT, g_Gt + 1 * (size_t)CHUNK_BYTES, CHUNK_BYTES, mb[1]);
    }

    // ---- X prologue: 128 x 512 f32 -> bf16, swizzled blocked atoms ----
    // (overlaps the first bulk DMAs)
    const float4* Xg = reinterpret_cast<const float4*>(X + (size_t)blockIdx.x * MT * NF);
#pragma unroll 4
    for (int it = 0; it < 32; it++) {
        int f = tid + it * NTHREADS;
        int r = f >> 7;             // 128 float4 per row
        int k = (f & 127) * 4;
        float4 x4 = Xg[f];
        __nv_bfloat162 lo, hi;
        lo.x = __float2bfloat16(x4.x); lo.y = __float2bfloat16(x4.y);
        hi.x = __float2bfloat16(x4.z); hi.y = __float2bfloat16(x4.w);
        uint2 u;
        u.x = *reinterpret_cast<uint32_t*>(&lo);
        u.y = *reinterpret_cast<uint32_t*>(&hi);
        *reinterpret_cast<uint2*>(smem + SM_X + sw128(aByte(r, k))) = u;
    }

    // ---- per-lane ldsm address constants (swizzle folded: disjoint bits) ----
    uint32_t koffA[4], koffB[4];
#pragma unroll
    for (int ks = 0; ks < 4; ks++) {
        koffA[ks] = ((uint32_t)((lane >> 4) << 4) | (ks << 5)) ^ ((lane & 7) << 4);
        koffB[ks] = ((uint32_t)(((lane >> 3) & 1) << 4) | (ks << 5)) ^ ((lane & 7) << 4);
    }
    uint32_t aRowB[2], bRowB[4];
#pragma unroll
    for (int mf = 0; mf < 2; mf++)
        aRowB[mf] = sb + SM_X +
            (uint32_t)(((wm * 4 + mf * 2 + ((lane >> 3) & 1)) << 10) | ((lane & 7) << 7));
#pragma unroll
    for (int nf = 0; nf < 4; nf++)
        bRowB[nf] = (uint32_t)(((wn * 8 + nf * 2 + ((lane >> 4) & 1)) << 10) | ((lane & 7) << 7));

    float acc[2][8][4];
    const float bias0 = bg[0];

#pragma unroll 1
    for (int t = 0; t < NCHUNK; t++) {
        mbar_wait(mb[t % 3], (uint32_t)((t / 3) & 1));   // chunk t DMA complete
        __syncthreads();   // all warps done reading chunk t-1 (slot (t+2)%3 free)
        if (t + 2 < NCHUNK && tid == 0) {
            uint32_t s2 = (uint32_t)((t + 2) % 3);
            MBAR_EXPECT_TX(mb[s2], CHUNK_BYTES);
            bulk_g2s(sb + SM_B + s2 * SM_B_SLOT,
                     g_Gt + (size_t)(t + 2) * CHUNK_BYTES, CHUNK_BYTES, mb[s2]);
        }

        if ((t & 7) == 0) {
            // init accumulators with w1 (folds linear term in)
            int jt = t >> 3;
#pragma unroll
            for (int nf8 = 0; nf8 < 8; nf8++) {
                int c = jt * NT + wn * 64 + nf8 * 8 + (lane & 3) * 2;
                float w0 = __ldg(&w1g[c]), w1v = __ldg(&w1g[c + 1]);
#pragma unroll
                for (int mf = 0; mf < 2; mf++) {
                    acc[mf][nf8][0] = w0;  acc[mf][nf8][1] = w1v;
                    acc[mf][nf8][2] = w0;  acc[mf][nf8][3] = w1v;
                }
            }
        }

        uint32_t slot = sb + SM_B + (uint32_t)(t % 3) * SM_B_SLOT;
        uint32_t aB[2], bB[4];
#pragma unroll
        for (int mf = 0; mf < 2; mf++) aB[mf] = aRowB[mf] + ((uint32_t)(t & 7) << 14);
#pragma unroll
        for (int nf = 0; nf < 4; nf++) bB[nf] = slot + bRowB[nf];

#pragma unroll
        for (int ks = 0; ks < 4; ks++) {
            uint32_t a[2][4], b[4][4];
#pragma unroll
            for (int mf = 0; mf < 2; mf++) ldsm4(a[mf], aB[mf] + koffA[ks]);
#pragma unroll
            for (int nf = 0; nf < 4; nf++) ldsm4(b[nf], bB[nf] + koffB[ks]);
#pragma unroll
            for (int mf = 0; mf < 2; mf++) {
#pragma unroll
                for (int nf = 0; nf < 4; nf++) {
                    mma16816(acc[mf][2 * nf],     a[mf], &b[nf][0]);
                    mma16816(acc[mf][2 * nf + 1], a[mf], &b[nf][2]);
                }
            }
        }

        if ((t & 7) == 7) {
            // ---- epilogue for this n-sweep: sum += acc . x  (w1 already in) ----
            int jt = t >> 3;
#pragma unroll
            for (int mf = 0; mf < 2; mf++) {
                int r0 = wm * 32 + mf * 16 + (lane >> 2);
                int r1 = r0 + 8;
                float pA = 0.f, pB = 0.f;
#pragma unroll
                for (int nf8 = 0; nf8 < 8; nf8++) {
                    int c = jt * NT + wn * 64 + nf8 * 8 + (lane & 3) * 2;
                    uint32_t xa = *reinterpret_cast<uint32_t*>(smem + SM_X + sw128(aByte(r0, c)));
                    uint32_t xb = *reinterpret_cast<uint32_t*>(smem + SM_X + sw128(aByte(r1, c)));
                    float x0 = __uint_as_float(xa << 16);
                    float x1 = __uint_as_float(xa & 0xffff0000u);
                    float y0 = __uint_as_float(xb << 16);
                    float y1 = __uint_as_float(xb & 0xffff0000u);
                    pA = fmaf(acc[mf][nf8][0], x0, pA);
                    pA = fmaf(acc[mf][nf8][1], x1, pA);
                    pB = fmaf(acc[mf][nf8][2], y0, pB);
                    pB = fmaf(acc[mf][nf8][3], y1, pB);
                }
                pA += __shfl_xor_sync(0xffffffffu, pA, 1);
                pA += __shfl_xor_sync(0xffffffffu, pA, 2);
                pB += __shfl_xor_sync(0xffffffffu, pB, 1);
                pB += __shfl_xor_sync(0xffffffffu, pB, 2);
                if ((lane & 3) == 0) {
                    atomicAdd(&accs[r0], pA);
                    atomicAdd(&accs[r1], pB);
                }
            }
        }
    }

    __syncthreads();
    if (tid < MT) {
        float logit = accs[tid] + bias0;
        out[blockIdx.x * MT + tid] = 1.f / (1.f + expf(-logit));
    }
}

// ---------------------------------------------------------------------------
// kernel_launch
//   inputs: X [B,512] f32, w1 [512,1] f32, b [1] f32,
//           v [512,30,40] f32, feature2field [512] i32 ; output [B] f32
// ---------------------------------------------------------------------------
extern "C" void kernel_launch(void* const* d_in, const int* in_sizes, int n_in,
                              void* d_out, int out_size) {
    const float* X   = (const float*)d_in[0];
    const float* w1  = (const float*)d_in[1];
    const float* b   = (const float*)d_in[2];
    const float* v   = (const float*)d_in[3];
    const int*   f2f = (const int*)d_in[4];
    float* out = (float*)d_out;
    (void)n_in; (void)out_size;

    int Brows = in_sizes[0] / NF;

    static bool attr_set = false;
    if (!attr_set) {
        cudaFuncSetAttribute(ffm_hmma_kernel,
                             cudaFuncAttributeMaxDynamicSharedMemorySize, SM_TOT);
        attr_set = true;
    }

    build_G_kernel<<<NF, NF>>>(v, f2f);
    ffm_hmma_kernel<<<Brows / MT, NTHREADS, SM_TOT>>>(X, w1, b, out);
}

// round 11
// speedup vs baseline: 1.3510x; 1.1050x over previous
#include <cuda_runtime.h>
#include <cuda_bf16.h>
#include <cstdint>
#include <math.h>

#define NF 512
#define NFIELD 30
#define KDIM 40
#define MT 128          // rows per CTA
#define NTHREADS 512

// ---- smem layout (bytes) ----
#define SM_X      0
#define SM_X_BYTES (MT * NF * 2)            // 131072
#define SM_ACC    (SM_X + SM_X_BYTES)
#define SM_TOT    (SM_ACC + MT * 4)         // 131584

// G in mma-fragment order:
//   element (n, k):  u=k>>6, g=n>>6, ks=(k>>4)&3, p=(n>>4)&3, h=(n>>3)&1,
//                    kk=k&15, l=((n&7)<<2)|((kk&7)>>1), w=kk>>3, q=h*2+w
//   byte = ((u*8+g)<<13) + ((ks*4+p)<<9) + (l<<4) + (q<<2) + ((kk&1)<<1)
// So lane l's uint4 at [u][g][ks][p] = frags (tile 2p: reg0,reg1, tile 2p+1: reg0,reg1).
__device__ __align__(128) unsigned char g_Gt[NF * NF * 2];

// ---------------- helpers ----------------
__device__ __forceinline__ uint32_t smem_u32(const void* p) {
    uint32_t a;
    asm("{ .reg .u64 t; cvta.to.shared.u64 t, %1; cvt.u32.u64 %0, t; }" : "=r"(a) : "l"(p));
    return a;
}
__device__ __forceinline__ uint32_t sw128(uint32_t b) { return b ^ ((b >> 3) & 0x70); }
// X tile: blocked atoms (8 rows x 64 bf16 = 1024B); atom = (r>>3) + (k>>6)*16
__device__ __forceinline__ uint32_t aByte(int r, int k) {
    return (uint32_t)((((r >> 3) + (k >> 6) * 16) << 10) + ((r & 7) << 7) + ((k & 63) << 1));
}
__device__ __forceinline__ void ldsm4(uint32_t* r, uint32_t addr) {
    asm volatile("ldmatrix.sync.aligned.m8n8.x4.shared.b16 {%0,%1,%2,%3}, [%4];"
                 : "=r"(r[0]), "=r"(r[1]), "=r"(r[2]), "=r"(r[3]) : "r"(addr));
}
__device__ __forceinline__ void mma16816(float* c, const uint32_t* a, uint32_t b0, uint32_t b1) {
    asm volatile(
        "mma.sync.aligned.m16n8k16.row.col.f32.bf16.bf16.f32 "
        "{%0,%1,%2,%3}, {%4,%5,%6,%7}, {%8,%9}, {%0,%1,%2,%3};"
        : "+f"(c[0]), "+f"(c[1]), "+f"(c[2]), "+f"(c[3])
        : "r"(a[0]), "r"(a[1]), "r"(a[2]), "r"(a[3]), "r"(b0), "r"(b1));
}

// ---------------------------------------------------------------------------
// Kernel 1: G symmetric; write BOTH mirrors directly into fragment order.
// ---------------------------------------------------------------------------
__device__ __forceinline__ void storeGt(int n, int k, __nv_bfloat16 h) {
    int u = k >> 6, g = n >> 6, ks = (k >> 4) & 3, p = (n >> 4) & 3;
    int hh = (n >> 3) & 1, kk = k & 15;
    int l = ((n & 7) << 2) | ((kk & 7) >> 1);
    int q = hh * 2 + (kk >> 3);
    uint32_t byte = ((uint32_t)((u << 3) | g) << 13) + ((uint32_t)((ks << 2) | p) << 9)
                  + ((uint32_t)l << 4) + ((uint32_t)q << 2) + ((uint32_t)(kk & 1) << 1);
    *reinterpret_cast<__nv_bfloat16*>(g_Gt + byte) = h;
}

__global__ void build_G_kernel(const float* __restrict__ v, const int* __restrict__ f2f) {
    int j = blockIdx.x;
    int i = threadIdx.x;
    if (i < j) return;
    int fj = __ldg(&f2f[j]);
    int fi = __ldg(&f2f[i]);
    const float4* a  = reinterpret_cast<const float4*>(v + ((size_t)i * NFIELD + fj) * KDIM);
    const float4* bp = reinterpret_cast<const float4*>(v + ((size_t)j * NFIELD + fi) * KDIM);
    float s = 0.f;
#pragma unroll
    for (int t = 0; t < KDIM / 4; t++) {
        float4 av = a[t], bv = bp[t];
        s = fmaf(av.x, bv.x, s);
        s = fmaf(av.y, bv.y, s);
        s = fmaf(av.z, bv.z, s);
        s = fmaf(av.w, bv.w, s);
    }
    s *= 0.5f;
    if (i == j) s = 0.f;
    __nv_bfloat16 h = __float2bfloat16(s);
    storeGt(j, i, h);   // B[n=j][k=i]
    storeGt(i, j, h);   // B[n=i][k=j]
}

// ---------------------------------------------------------------------------
// Kernel 2: HMMA quadratic form, barrier-free mainloop.
//   16 warps: wm = wid&3 (4 x 32 rows), wn = wid>>2 (4 n-blocks of 64).
//   2 sweeps (jt): n-block g = jt*4 + wn. B frags via direct LDG.128 from
//   fragment-ordered g_Gt (L2/L1 resident). A via ldsm from X smem tile.
// ---------------------------------------------------------------------------
__global__ __launch_bounds__(NTHREADS, 1)
void ffm_hmma_kernel(const float* __restrict__ X, const float* __restrict__ w1g,
                     const float* __restrict__ bg, float* __restrict__ out) {
    extern __shared__ __align__(1024) char smem[];
    const int tid  = threadIdx.x;
    const int lane = tid & 31;
    const int wid  = tid >> 5;
    const int wm   = wid & 3;
    const int wn   = wid >> 2;

    uint32_t sb = smem_u32(smem);
    float* accs = reinterpret_cast<float*>(smem + SM_ACC);
    if (tid < MT) accs[tid] = 0.f;

    // ---- X prologue: 128 x 512 f32 -> bf16, swizzled blocked atoms ----
    const float4* Xg = reinterpret_cast<const float4*>(X + (size_t)blockIdx.x * MT * NF);
#pragma unroll 4
    for (int it = 0; it < 32; it++) {
        int f = tid + it * NTHREADS;
        int r = f >> 7;             // 128 float4 per row
        int k = (f & 127) * 4;
        float4 x4 = Xg[f];
        __nv_bfloat162 lo, hi;
        lo.x = __float2bfloat16(x4.x); lo.y = __float2bfloat16(x4.y);
        hi.x = __float2bfloat16(x4.z); hi.y = __float2bfloat16(x4.w);
        uint2 u2;
        u2.x = *reinterpret_cast<uint32_t*>(&lo);
        u2.y = *reinterpret_cast<uint32_t*>(&hi);
        *reinterpret_cast<uint2*>(smem + SM_X + sw128(aByte(r, k))) = u2;
    }
    __syncthreads();   // the ONLY barrier before the epilogue

    // ---- per-lane ldsm address constants (swizzle folded: disjoint bits) ----
    uint32_t koffA[4];
#pragma unroll
    for (int ks = 0; ks < 4; ks++)
        koffA[ks] = ((uint32_t)((lane >> 4) << 4) | (ks << 5)) ^ ((lane & 7) << 4);
    uint32_t aRowB[2];
#pragma unroll
    for (int mf = 0; mf < 2; mf++)
        aRowB[mf] = sb + SM_X +
            (uint32_t)(((wm * 4 + mf * 2 + ((lane >> 3) & 1)) << 10) | ((lane & 7) << 7));

    float acc[2][8][4];
    const float bias0 = bg[0];

#pragma unroll 1
    for (int jt = 0; jt < 2; jt++) {
        const int g = jt * 4 + wn;

        // init accumulators with w1 (folds linear term in)
#pragma unroll
        for (int nf8 = 0; nf8 < 8; nf8++) {
            int c = g * 64 + nf8 * 8 + (lane & 3) * 2;
            float w0 = __ldg(&w1g[c]), w1v = __ldg(&w1g[c + 1]);
#pragma unroll
            for (int mf = 0; mf < 2; mf++) {
                acc[mf][nf8][0] = w0;  acc[mf][nf8][1] = w1v;
                acc[mf][nf8][2] = w0;  acc[mf][nf8][3] = w1v;
            }
        }

#pragma unroll 2
        for (int u = 0; u < 8; u++) {
            const uint4* gw = reinterpret_cast<const uint4*>(
                g_Gt + (((uint32_t)((u << 3) | g)) << 13) + ((uint32_t)lane << 4));
#pragma unroll
            for (int ks = 0; ks < 4; ks++) {
                uint4 bq[4];
#pragma unroll
                for (int p = 0; p < 4; p++)
                    bq[p] = __ldg(gw + ((ks * 4 + p) << 5));
                uint32_t a[2][4];
#pragma unroll
                for (int mf = 0; mf < 2; mf++)
                    ldsm4(a[mf], aRowB[mf] + ((uint32_t)u << 14) + koffA[ks]);
#pragma unroll
                for (int mf = 0; mf < 2; mf++) {
#pragma unroll
                    for (int p = 0; p < 4; p++) {
                        mma16816(acc[mf][2 * p],     a[mf], bq[p].x, bq[p].y);
                        mma16816(acc[mf][2 * p + 1], a[mf], bq[p].z, bq[p].w);
                    }
                }
            }
        }

        // ---- epilogue for this sweep: sum += acc . x  (w1 already in) ----
#pragma unroll
        for (int mf = 0; mf < 2; mf++) {
            int r0 = wm * 32 + mf * 16 + (lane >> 2);
            int r1 = r0 + 8;
            float pA = 0.f, pB = 0.f;
#pragma unroll
            for (int nf8 = 0; nf8 < 8; nf8++) {
                int c = g * 64 + nf8 * 8 + (lane & 3) * 2;
                uint32_t xa = *reinterpret_cast<uint32_t*>(smem + SM_X + sw128(aByte(r0, c)));
                uint32_t xb = *reinterpret_cast<uint32_t*>(smem + SM_X + sw128(aByte(r1, c)));
                float x0 = __uint_as_float(xa << 16);
                float x1 = __uint_as_float(xa & 0xffff0000u);
                float y0 = __uint_as_float(xb << 16);
                float y1 = __uint_as_float(xb & 0xffff0000u);
                pA = fmaf(acc[mf][nf8][0], x0, pA);
                pA = fmaf(acc[mf][nf8][1], x1, pA);
                pB = fmaf(acc[mf][nf8][2], y0, pB);
                pB = fmaf(acc[mf][nf8][3], y1, pB);
            }
            pA += __shfl_xor_sync(0xffffffffu, pA, 1);
            pA += __shfl_xor_sync(0xffffffffu, pA, 2);
            pB += __shfl_xor_sync(0xffffffffu, pB, 1);
            pB += __shfl_xor_sync(0xffffffffu, pB, 2);
            if ((lane & 3) == 0) {
                atomicAdd(&accs[r0], pA);
                atomicAdd(&accs[r1], pB);
            }
        }
    }

    __syncthreads();
    if (tid < MT) {
        float logit = accs[tid] + bias0;
        out[blockIdx.x * MT + tid] = 1.f / (1.f + expf(-logit));
    }
}

// ---------------------------------------------------------------------------
// kernel_launch
//   inputs: X [B,512] f32, w1 [512,1] f32, b [1] f32,
//           v [512,30,40] f32, feature2field [512] i32 ; output [B] f32
// ---------------------------------------------------------------------------
extern "C" void kernel_launch(void* const* d_in, const int* in_sizes, int n_in,
                              void* d_out, int out_size) {
    const float* X   = (const float*)d_in[0];
    const float* w1  = (const float*)d_in[1];
    const float* b   = (const float*)d_in[2];
    const float* v   = (const float*)d_in[3];
    const int*   f2f = (const int*)d_in[4];
    float* out = (float*)d_out;
    (void)n_in; (void)out_size;

    int Brows = in_sizes[0] / NF;

    static bool attr_set = false;
    if (!attr_set) {
        cudaFuncSetAttribute(ffm_hmma_kernel,
                             cudaFuncAttributeMaxDynamicSharedMemorySize, SM_TOT);
        attr_set = true;
    }

    build_G_kernel<<<NF, NF>>>(v, f2f);
    ffm_hmma_kernel<<<Brows / MT, NTHREADS, SM_TOT>>>(X, w1, b, out);
}